// round 17
// baseline (speedup 1.0000x reference)
#include <cuda_runtime.h>
#include <cuda_bf16.h>
#include <cuda_fp16.h>
#include <math.h>
#include <stdint.h>

// Problem constants
#define NTOK 2048          // B*T
#define SEQ  1024
#define DMODEL 768
#define NHEAD 12
#define HDIM 64
#define NLAYER 8
#define VOCAB 50257
#define VPAD  50304        // 393*128
#define NBT   (VPAD / 128) // 393 lm_head column tiles

// per-layer transposed-weight plane offsets (elements)
#define OFF_ATTN  0
#define SZ_ATTN   (3 * DMODEL * DMODEL)
#define OFF_PROJ  (NLAYER * SZ_ATTN)
#define SZ_PROJ   (DMODEL * DMODEL)
#define OFF_FC    (OFF_PROJ + NLAYER * SZ_PROJ)
#define SZ_FC     (4 * DMODEL * DMODEL)
#define OFF_PROJ2 (OFF_FC + NLAYER * SZ_FC)
#define SZ_PROJ2  (4 * DMODEL * DMODEL)
#define WT_TOTAL  (OFF_PROJ2 + NLAYER * SZ_PROJ2)

// ---------------- scratch (device globals; no allocation allowed) ------------
__device__ float g_x[NTOK * DMODEL];
__device__ float g_rowloss[NTOK];
__device__ float2 g_lpart[NTOK * NBT];         // lm_head loss partials (max, sumexp)
__device__ __half g_h16[NTOK * DMODEL];        // LN out (fp16)
__device__ __half g_y16[NTOK * DMODEL];        // attn out (fp16)
__device__ __half g_m16[NTOK * 4 * DMODEL];    // mlp hidden (fp16)
__device__ __half g_qkv16[NTOK * 3 * DMODEL];  // qkv (fp16)
__device__ __half g_wT16[WT_TOTAL];            // transposed weights (fp16)
__device__ __half g_wte16[(size_t)VPAD * DMODEL];

// ---------------- helpers -----------------------------------------------------
__device__ __forceinline__ uint32_t smem_u32(const void* p) {
    uint32_t a;
    asm("{ .reg .u64 t; cvta.to.shared.u64 t, %1; cvt.u32.u64 %0, t; }" : "=r"(a) : "l"(p));
    return a;
}

#define CP_ASYNC16(s, g) \
    asm volatile("cp.async.cg.shared.global [%0], [%1], 16;" :: "r"(s), "l"(g) : "memory")
#define CP_COMMIT() asm volatile("cp.async.commit_group;" ::: "memory")

__device__ __forceinline__ void ldsm4(uint32_t r[4], uint32_t addr) {
    asm volatile("ldmatrix.sync.aligned.m8n8.x4.shared.b16 {%0,%1,%2,%3}, [%4];"
        : "=r"(r[0]), "=r"(r[1]), "=r"(r[2]), "=r"(r[3]) : "r"(addr));
}
__device__ __forceinline__ void ldsm4t(uint32_t r[4], uint32_t addr) {
    asm volatile("ldmatrix.sync.aligned.m8n8.x4.trans.shared.b16 {%0,%1,%2,%3}, [%4];"
        : "=r"(r[0]), "=r"(r[1]), "=r"(r[2]), "=r"(r[3]) : "r"(addr));
}
__device__ __forceinline__ void mma_f16(float c[4], const uint32_t a[4],
                                        uint32_t b0, uint32_t b1) {
    asm volatile("mma.sync.aligned.m16n8k16.row.col.f32.f16.f16.f32 "
        "{%0,%1,%2,%3}, {%4,%5,%6,%7}, {%8,%9}, {%0,%1,%2,%3};"
        : "+f"(c[0]), "+f"(c[1]), "+f"(c[2]), "+f"(c[3])
        : "r"(a[0]), "r"(a[1]), "r"(a[2]), "r"(a[3]), "r"(b0), "r"(b1));
}

// pack two fp32 into one u32 of fp16x2 (elem0 low)
__device__ __forceinline__ uint32_t pack_h2(float a, float b) {
    __half2 h = __floats2half2_rn(a, b);
    uint32_t u;
    memcpy(&u, &h, 4);
    return u;
}

__device__ __forceinline__ float gelu_f(float x) {
    const float c = 0.7978845608028654f;
    float x3 = x * x * x;
    return 0.5f * x * (1.0f + tanhf(c * (x + 0.044715f * x3)));
}

// online logsumexp
__device__ __forceinline__ void lse_add(float& m, float& s, float v) {
    float nm = fmaxf(m, v);
    s = s * __expf(m - nm) + __expf(v - nm);
    m = nm;
}
__device__ __forceinline__ void lse_merge(float& m, float& s, float m2, float s2) {
    float nm = fmaxf(m, m2);
    s = s * __expf(m - nm) + s2 * __expf(m2 - nm);
    m = nm;
}

// ---------------- fp16 single-plane GEMM --------------------------------------
// C[M,N] = A[M,K]*B^T, fp16 operands, fp32 accum. CTA tile MTx128, 512 threads
// (16 warps, warp tile (MT/4)x32), KC=64, 4-stage cp.async, single barrier/chunk.
// MT=128 path additionally double-buffers ldsm fragments across ks-steps.
// EPI: 0 = lm_head: plain f32 out (N-pred) + fused logsumexp partials
//      1 = +bias -> fp16 plane (qkv); 2 = gelu(+bias) -> fp16 plane (fc);
//      3 = +bias, residual f32 C += (proj / proj2)
#define KC 64
#define NSTG 4

template <int EPI, int MT>
__global__ void __launch_bounds__(512, 1)
gemm_f16(const __half* __restrict__ A, const __half* __restrict__ B,
         const float* __restrict__ bias, float* __restrict__ C,
         __half* __restrict__ CF, int N, int K) {
    constexpr int MI  = MT / 64;          // a-frag groups per warp (2 or 4)
    constexpr int APL = MT * 128;         // A plane bytes
    constexpr int STG = APL + 16384;      // stage bytes (A + B(128 rows))

    extern __shared__ char dsm[];
    uint32_t sb = (smem_u32(dsm) + 127) & ~127u;

    const int tid = threadIdx.x;
    const int wid = tid >> 5, lid = tid & 31;
    const long bm = (long)blockIdx.x * MT;
    const long bn = (long)blockIdx.y * 128;
    const int wm = (wid >> 2) * (MT / 4);
    const int wn = (wid & 3) * 32;
    const int lrow = lid & 15, lg = lid >> 4;

    const int nch = K / KC;

    auto load_stage = [&](int c) {
        uint32_t stb = sb + (c % NSTG) * STG;
        int kc0 = c * KC;
        #pragma unroll
        for (int u = tid; u < MT * 8; u += 512) {
            int row = u >> 3, g = u & 7;
            CP_ASYNC16(stb + row * 128 + ((g ^ (row & 7)) << 4),
                       A + (bm + row) * (long)K + kc0 + g * 8);
        }
        #pragma unroll
        for (int u = tid; u < 128 * 8; u += 512) {
            int row = u >> 3, g = u & 7;
            CP_ASYNC16(stb + APL + row * 128 + ((g ^ (row & 7)) << 4),
                       B + (bn + row) * (long)K + kc0 + g * 8);
        }
        CP_COMMIT();
    };

    float creg[MI][4][4];
    #pragma unroll
    for (int a = 0; a < MI; a++)
        #pragma unroll
        for (int b = 0; b < 4; b++)
            #pragma unroll
            for (int k = 0; k < 4; k++) creg[a][b][k] = 0.f;

    load_stage(0);
    load_stage(1);
    load_stage(2);

    for (int c = 0; c < nch; c++) {
        int rem = nch - 1 - c;
        if (rem >= 2)      { asm volatile("cp.async.wait_group 2;" ::: "memory"); }
        else if (rem == 1) { asm volatile("cp.async.wait_group 1;" ::: "memory"); }
        else               { asm volatile("cp.async.wait_group 0;" ::: "memory"); }
        __syncthreads();
        if (c + 3 < nch) load_stage(c + 3);   // targets buffer freed by chunk c-1

        uint32_t stb = sb + (c % NSTG) * STG;
        if (MI == 2) {
            // fragment double-buffered pipeline over ks-steps
            uint32_t aF[2][MI][4], bF[2][2][4];
            auto ldfrags = [&](int ks, int buf) {
                int g = 2 * ks + lg;
                #pragma unroll
                for (int mi = 0; mi < MI; mi++) {
                    int row = wm + mi * 16 + lrow;
                    ldsm4(aF[buf][mi], stb + row * 128 + ((g ^ (row & 7)) << 4));
                }
                #pragma unroll
                for (int ng = 0; ng < 2; ng++) {
                    int row = wn + ng * 16 + lrow;
                    ldsm4(bF[buf][ng], stb + APL + row * 128 + ((g ^ (row & 7)) << 4));
                }
            };
            ldfrags(0, 0);
            #pragma unroll
            for (int ks = 0; ks < 4; ks++) {
                if (ks < 3) ldfrags(ks + 1, (ks + 1) & 1);
                int buf = ks & 1;
                #pragma unroll
                for (int mi = 0; mi < MI; mi++)
                    #pragma unroll
                    for (int ni = 0; ni < 4; ni++) {
                        int ng = ni >> 1, h = ni & 1;
                        mma_f16(creg[mi][ni], aF[buf][mi], bF[buf][ng][h], bF[buf][ng][h + 2]);
                    }
            }
        } else {
            #pragma unroll
            for (int ks = 0; ks < 4; ks++) {
                int g = 2 * ks + lg;
                uint32_t aF[MI][4], bF[2][4];
                #pragma unroll
                for (int mi = 0; mi < MI; mi++) {
                    int row = wm + mi * 16 + lrow;
                    ldsm4(aF[mi], stb + row * 128 + ((g ^ (row & 7)) << 4));
                }
                #pragma unroll
                for (int ng = 0; ng < 2; ng++) {
                    int row = wn + ng * 16 + lrow;
                    ldsm4(bF[ng], stb + APL + row * 128 + ((g ^ (row & 7)) << 4));
                }
                #pragma unroll
                for (int mi = 0; mi < MI; mi++)
                    #pragma unroll
                    for (int ni = 0; ni < 4; ni++) {
                        int ng = ni >> 1, h = ni & 1;
                        mma_f16(creg[mi][ni], aF[mi], bF[ng][h], bF[ng][h + 2]);
                    }
            }
        }
    }

    // ---- epilogue ----
    int gid = lid >> 2, tin = lid & 3;
    if (EPI == 0) {
        // lm_head: logits + per-row logsumexp partials
        float pm[MI][2], ps[MI][2];
        #pragma unroll
        for (int a = 0; a < MI; a++)
            #pragma unroll
            for (int b = 0; b < 2; b++) { pm[a][b] = -1e30f; ps[a][b] = 0.f; }

        #pragma unroll
        for (int mi = 0; mi < MI; mi++) {
            long row0 = bm + wm + mi * 16 + gid;
            long row1 = row0 + 8;
            #pragma unroll
            for (int ni = 0; ni < 4; ni++) {
                long col = bn + wn + ni * 8 + tin * 2;
                float v0 = creg[mi][ni][0];
                float v1 = creg[mi][ni][1];
                float v2 = creg[mi][ni][2];
                float v3 = creg[mi][ni][3];
                if (col < N) {
                    C[row0 * N + col] = v0; C[row1 * N + col] = v2;
                    lse_add(pm[mi][0], ps[mi][0], v0);
                    lse_add(pm[mi][1], ps[mi][1], v2);
                }
                if (col + 1 < N) {
                    C[row0 * N + col + 1] = v1; C[row1 * N + col + 1] = v3;
                    lse_add(pm[mi][0], ps[mi][0], v1);
                    lse_add(pm[mi][1], ps[mi][1], v3);
                }
            }
        }
        float2* buf = (float2*)dsm;
        int unit = (wid & 3) * 4 + tin;
        __syncthreads();
        #pragma unroll
        for (int mi = 0; mi < MI; mi++)
            #pragma unroll
            for (int rh = 0; rh < 2; rh++) {
                int rit = wm + mi * 16 + gid + rh * 8;
                buf[rit * 16 + unit] = make_float2(pm[mi][rh], ps[mi][rh]);
            }
        __syncthreads();
        if (tid < MT) {
            float m = -1e30f, s = 0.f;
            #pragma unroll
            for (int u = 0; u < 16; u++) {
                float2 p = buf[tid * 16 + u];
                lse_merge(m, s, p.x, p.y);
            }
            g_lpart[(bm + tid) * NBT + blockIdx.y] = make_float2(m, s);
        }
    } else {
        #pragma unroll
        for (int mi = 0; mi < MI; mi++) {
            long row0 = bm + wm + mi * 16 + gid;
            long row1 = row0 + 8;
            #pragma unroll
            for (int ni = 0; ni < 4; ni++) {
                long col = bn + wn + ni * 8 + tin * 2;
                float b0 = bias[col], b1 = bias[col + 1];
                float v0 = creg[mi][ni][0] + b0;
                float v1 = creg[mi][ni][1] + b1;
                float v2 = creg[mi][ni][2] + b0;
                float v3 = creg[mi][ni][3] + b1;
                size_t o0 = (size_t)row0 * N + col;
                size_t o1 = (size_t)row1 * N + col;
                if (EPI == 1) {
                    *(__half2*)&CF[o0] = __floats2half2_rn(v0, v1);
                    *(__half2*)&CF[o1] = __floats2half2_rn(v2, v3);
                } else if (EPI == 2) {
                    *(__half2*)&CF[o0] = __floats2half2_rn(gelu_f(v0), gelu_f(v1));
                    *(__half2*)&CF[o1] = __floats2half2_rn(gelu_f(v2), gelu_f(v3));
                } else {
                    float2 c0 = *(float2*)&C[o0];
                    float2 c1 = *(float2*)&C[o1];
                    *(float2*)&C[o0] = make_float2(v0 + c0.x, v1 + c0.y);
                    *(float2*)&C[o1] = make_float2(v2 + c1.x, v3 + c1.y);
                }
            }
        }
    }
}

#define SM_128 (NSTG * (128 * 128 + 16384) + 128)   // 131200
#define SM_256 (NSTG * (256 * 128 + 16384) + 128)   // 196736

// ---------------- fp16 flash attention -----------------------------------------
// grid (SEQ/64, NHEAD, B), 128 threads. Reversed x order: longest KV first.
// smem: Q(8K) | stage{0,1}: K(8K) V(8K)
#define ATT_SMEM (8192 + 2 * 16384 + 128)

__global__ void __launch_bounds__(128, 4)
attn_tc(const __half* __restrict__ QKV, __half* __restrict__ Y) {
    extern __shared__ char dsm[];
    uint32_t sb = (smem_u32(dsm) + 127) & ~127u;

    const int tid = threadIdx.x;
    const int wid = tid >> 5, lid = tid & 31;
    const int qtile = gridDim.x - 1 - blockIdx.x;   // heavy blocks first
    const int q0 = qtile * 64, h = blockIdx.y, b = blockIdx.z;
    const int wq = wid * 16;
    const int ntile = qtile + 1;
    const size_t rstride = 3 * DMODEL;

    auto ldplane = [&](uint32_t dst, const __half* src) {
        #pragma unroll
        for (int i = 0; i < 4; i++) {
            int u = tid + 128 * i;
            int row = u >> 3, ch = u & 7;
            CP_ASYNC16(dst + row * 128 + ((ch ^ (row & 7)) << 4),
                       src + (size_t)row * rstride + ch * 8);
        }
    };
    auto ldstage = [&](int t) {
        uint32_t s = sb + 8192 + (t & 1) * 16384;
        size_t off = (size_t)(b * SEQ + t * 64) * rstride + h * HDIM;
        ldplane(s,        QKV + off + DMODEL);       // K
        ldplane(s + 8192, QKV + off + 2 * DMODEL);   // V
        CP_COMMIT();
    };

    {
        size_t qoff = (size_t)(b * SEQ + q0) * rstride + h * HDIM;
        ldplane(sb, QKV + qoff);
    }
    ldstage(0);

    float o[8][4];
    #pragma unroll
    for (int nb = 0; nb < 8; nb++)
        #pragma unroll
        for (int j = 0; j < 4; j++) o[nb][j] = 0.f;
    float mrun[2] = {-1e30f, -1e30f}, lrun[2] = {0.f, 0.f};

    for (int t = 0; t < ntile; t++) {
        asm volatile("cp.async.wait_group 0;" ::: "memory");
        __syncthreads();
        if (t + 1 < ntile) ldstage(t + 1);
        uint32_t kb = sb + 8192 + (t & 1) * 16384;

        float s[8][4];
        #pragma unroll
        for (int nb = 0; nb < 8; nb++)
            #pragma unroll
            for (int j = 0; j < 4; j++) s[nb][j] = 0.f;

        #pragma unroll
        for (int ks = 0; ks < 4; ks++) {
            uint32_t qf[4];
            {
                int r = wq + (lid & 15);
                uint32_t off = r * 128 + (((2 * ks + (lid >> 4)) ^ (r & 7)) << 4);
                ldsm4(qf, sb + off);
            }
            #pragma unroll
            for (int ng = 0; ng < 4; ng++) {
                int r = ng * 16 + (lid & 15);
                uint32_t off = r * 128 + (((2 * ks + (lid >> 4)) ^ (r & 7)) << 4);
                uint32_t kf[4];
                ldsm4(kf, kb + off);
                mma_f16(s[2 * ng],     qf, kf[0], kf[2]);
                mma_f16(s[2 * ng + 1], qf, kf[1], kf[3]);
            }
        }

        #pragma unroll
        for (int nb = 0; nb < 8; nb++)
            #pragma unroll
            for (int j = 0; j < 4; j++) s[nb][j] *= 0.125f;

        if (t == ntile - 1) {
            int r0g = q0 + wq + (lid >> 2);
            #pragma unroll
            for (int nb = 0; nb < 8; nb++) {
                int colg = t * 64 + nb * 8 + (lid & 3) * 2;
                if (colg     > r0g)     s[nb][0] = -1e30f;
                if (colg + 1 > r0g)     s[nb][1] = -1e30f;
                if (colg     > r0g + 8) s[nb][2] = -1e30f;
                if (colg + 1 > r0g + 8) s[nb][3] = -1e30f;
            }
        }

        #pragma unroll
        for (int half = 0; half < 2; half++) {
            float mx = -1e30f;
            #pragma unroll
            for (int nb = 0; nb < 8; nb++)
                mx = fmaxf(mx, fmaxf(s[nb][2 * half], s[nb][2 * half + 1]));
            mx = fmaxf(mx, __shfl_xor_sync(~0u, mx, 1));
            mx = fmaxf(mx, __shfl_xor_sync(~0u, mx, 2));
            float mn = fmaxf(mrun[half], mx);
            float al = __expf(mrun[half] - mn);
            mrun[half] = mn;
            float sum = 0.f;
            #pragma unroll
            for (int nb = 0; nb < 8; nb++) {
                float p0 = __expf(s[nb][2 * half]     - mn);
                float p1 = __expf(s[nb][2 * half + 1] - mn);
                s[nb][2 * half] = p0; s[nb][2 * half + 1] = p1;
                sum += p0 + p1;
            }
            lrun[half] = lrun[half] * al + sum;
            #pragma unroll
            for (int nb = 0; nb < 8; nb++) {
                o[nb][2 * half] *= al; o[nb][2 * half + 1] *= al;
            }
        }

        #pragma unroll
        for (int kk = 0; kk < 4; kk++) {
            uint32_t pf[4];
            pf[0] = pack_h2(s[2 * kk][0],     s[2 * kk][1]);
            pf[1] = pack_h2(s[2 * kk][2],     s[2 * kk][3]);
            pf[2] = pack_h2(s[2 * kk + 1][0], s[2 * kk + 1][1]);
            pf[3] = pack_h2(s[2 * kk + 1][2], s[2 * kk + 1][3]);
            #pragma unroll
            for (int cc = 0; cc < 4; cc++) {
                int r = kk * 16 + (lid & 15);
                uint32_t off = r * 128 + (((2 * cc + (lid >> 4)) ^ (r & 7)) << 4);
                uint32_t vf[4];
                ldsm4t(vf, kb + 8192 + off);
                mma_f16(o[2 * cc],     pf, vf[0], vf[1]);
                mma_f16(o[2 * cc + 1], pf, vf[2], vf[3]);
            }
        }
    }

    float inv[2];
    #pragma unroll
    for (int half = 0; half < 2; half++) {
        float l = lrun[half];
        l += __shfl_xor_sync(~0u, l, 1);
        l += __shfl_xor_sync(~0u, l, 2);
        inv[half] = 1.0f / l;
    }
    int r0 = q0 + wq + (lid >> 2);
    #pragma unroll
    for (int nb = 0; nb < 8; nb++) {
        int col = h * HDIM + nb * 8 + (lid & 3) * 2;
        size_t o0 = (size_t)(b * SEQ + r0) * DMODEL + col;
        size_t o1 = (size_t)(b * SEQ + r0 + 8) * DMODEL + col;
        *(__half2*)&Y[o0] = __floats2half2_rn(o[nb][0] * inv[0], o[nb][1] * inv[0]);
        *(__half2*)&Y[o1] = __floats2half2_rn(o[nb][2] * inv[1], o[nb][3] * inv[1]);
    }
}

// ---------------- weight conversions ------------------------------------------
__global__ void cvt_wte16(const float* __restrict__ wte) {
    size_t i = (size_t)blockIdx.x * 256 + threadIdx.x;
    if (i >= (size_t)VPAD * DMODEL) return;
    float v = (i < (size_t)VOCAB * DMODEL) ? wte[i] : 0.0f;
    g_wte16[i] = __float2half_rn(v);
}

// w [L,K,N] f32 -> out [L,N,K] fp16. grid (N/32, K/32, L), block (32,8)
__global__ void cvt_wT16(const float* __restrict__ w, __half* __restrict__ tf,
                         int K, int N) {
    __shared__ float t[32][33];
    const float* wsrc = w + (size_t)blockIdx.z * K * N;
    __half* tfd = tf + (size_t)blockIdx.z * N * K;
    int n0 = blockIdx.x * 32, k0 = blockIdx.y * 32;
    int tx = threadIdx.x, ty = threadIdx.y;
    #pragma unroll
    for (int i = 0; i < 4; i++)
        t[ty + 8 * i][tx] = wsrc[(size_t)(k0 + ty + 8 * i) * N + n0 + tx];
    __syncthreads();
    #pragma unroll
    for (int i = 0; i < 4; i++) {
        size_t o = (size_t)(n0 + ty + 8 * i) * K + k0 + tx;
        tfd[o] = __float2half_rn(t[tx][ty + 8 * i]);
    }
}

// ---------------- embedding --------------------------------------------------
__global__ void embed_kernel(const int* __restrict__ idx,
                             const float* __restrict__ wte,
                             const float* __restrict__ wpe) {
    int row = blockIdx.x;
    int t = row & (SEQ - 1);
    int tok = idx[row];
    const float* we = wte + (size_t)tok * DMODEL;
    const float* wp = wpe + (size_t)t * DMODEL;
    float* xr = g_x + (size_t)row * DMODEL;
    for (int d = threadIdx.x; d < DMODEL; d += blockDim.x)
        xr[d] = we[d] + wp[d];
}

// ---------------- layernorm (writes fp16 plane) -------------------------------
__global__ void __launch_bounds__(256) ln_kernel(const float* __restrict__ x,
                                                 const float* __restrict__ sc,
                                                 const float* __restrict__ bi,
                                                 __half* __restrict__ outF) {
    __shared__ float red[8];
    int row = blockIdx.x, tid = threadIdx.x;
    const float* xr = x + (size_t)row * DMODEL;
    float v0 = xr[tid], v1 = xr[tid + 256], v2 = xr[tid + 512];

    float s = v0 + v1 + v2;
    #pragma unroll
    for (int o = 16; o > 0; o >>= 1) s += __shfl_xor_sync(~0u, s, o);
    if ((tid & 31) == 0) red[tid >> 5] = s;
    __syncthreads();
    if (tid < 32) {
        float t = (tid < 8) ? red[tid] : 0.f;
        #pragma unroll
        for (int o = 4; o > 0; o >>= 1) t += __shfl_xor_sync(~0u, t, o);
        if (tid == 0) red[0] = t;
    }
    __syncthreads();
    float mu = red[0] * (1.0f / DMODEL);
    __syncthreads();

    float d0 = v0 - mu, d1 = v1 - mu, d2 = v2 - mu;
    float s2 = d0 * d0 + d1 * d1 + d2 * d2;
    #pragma unroll
    for (int o = 16; o > 0; o >>= 1) s2 += __shfl_xor_sync(~0u, s2, o);
    if ((tid & 31) == 0) red[tid >> 5] = s2;
    __syncthreads();
    if (tid < 32) {
        float t = (tid < 8) ? red[tid] : 0.f;
        #pragma unroll
        for (int o = 4; o > 0; o >>= 1) t += __shfl_xor_sync(~0u, t, o);
        if (tid == 0) red[0] = t;
    }
    __syncthreads();
    float var = red[0] * (1.0f / DMODEL);
    float rs = rsqrtf(var + 1e-5f);

    size_t base = (size_t)row * DMODEL;
    #pragma unroll
    for (int e = 0; e < 3; e++) {
        float d = (e == 0) ? d0 : (e == 1) ? d1 : d2;
        int c = tid + 256 * e;
        outF[base + c] = __float2half_rn(d * rs * sc[c] + bi[c]);
    }
}

// ---------------- loss: merge lm_head partials --------------------------------
__global__ void __launch_bounds__(128) lossrow2(const float* __restrict__ logits,
                                                const int* __restrict__ targets) {
    int row = blockIdx.x;
    int tid = threadIdx.x;
    const float2* p = g_lpart + (size_t)row * NBT;
    float m = -1e30f, s = 0.f;
    for (int i = tid; i < NBT; i += 128) {
        float2 v = p[i];
        lse_merge(m, s, v.x, v.y);
    }
    __shared__ float sm[128], ss[128];
    sm[tid] = m; ss[tid] = s;
    __syncthreads();
    for (int st = 64; st > 0; st >>= 1) {
        if (tid < st) {
            float ma = sm[tid], sa = ss[tid];
            float mb = sm[tid + st], sb = ss[tid + st];
            float M = fmaxf(ma, mb);
            ss[tid] = sa * __expf(ma - M) + sb * __expf(mb - M);
            sm[tid] = M;
        }
        __syncthreads();
    }
    if (tid == 0) {
        float lse = sm[0] + logf(ss[0]);
        g_rowloss[row] = lse - logits[(size_t)row * VOCAB + targets[row]];
    }
}

__global__ void __launch_bounds__(256) lossreduce_kernel(float* __restrict__ out_loss) {
    __shared__ float red[8];
    float s = 0.f;
    for (int i = threadIdx.x; i < NTOK; i += 256) s += g_rowloss[i];
    #pragma unroll
    for (int o = 16; o > 0; o >>= 1) s += __shfl_xor_sync(~0u, s, o);
    if ((threadIdx.x & 31) == 0) red[threadIdx.x >> 5] = s;
    __syncthreads();
    if (threadIdx.x == 0) {
        float t = 0.f;
        for (int w = 0; w < 8; w++) t += red[w];
        out_loss[0] = t * (1.0f / NTOK);
    }
}

// ---------------- host orchestration -----------------------------------------
extern "C" void kernel_launch(void* const* d_in, const int* in_sizes, int n_in,
                              void* d_out, int out_size) {
    const int*   idx     = (const int*)  d_in[0];
    const int*   targets = (const int*)  d_in[1];
    const float* wte     = (const float*)d_in[2];
    const float* wpe     = (const float*)d_in[3];
    const float* ln1_s   = (const float*)d_in[4];
    const float* ln1_b   = (const float*)d_in[5];
    const float* attn_w  = (const float*)d_in[6];
    const float* attn_b  = (const float*)d_in[7];
    const float* proj_w  = (const float*)d_in[8];
    const float* proj_b  = (const float*)d_in[9];
    const float* ln2_s   = (const float*)d_in[10];
    const float* ln2_b   = (const float*)d_in[11];
    const float* fc_w    = (const float*)d_in[12];
    const float* fc_b    = (const float*)d_in[13];
    const float* proj2_w = (const float*)d_in[14];
    const float* proj2_b = (const float*)d_in[15];
    const float* lnf_s   = (const float*)d_in[16];
    const float* lnf_b   = (const float*)d_in[17];
    float* out = (float*)d_out;

    float* px;
    __half *ph16, *py16, *pm16, *pq16, *pwT16, *pwte16;
    cudaGetSymbolAddress((void**)&px, g_x);
    cudaGetSymbolAddress((void**)&ph16, g_h16);
    cudaGetSymbolAddress((void**)&py16, g_y16);
    cudaGetSymbolAddress((void**)&pm16, g_m16);
    cudaGetSymbolAddress((void**)&pq16, g_qkv16);
    cudaGetSymbolAddress((void**)&pwT16, g_wT16);
    cudaGetSymbolAddress((void**)&pwte16, g_wte16);

    cudaFuncSetAttribute(gemm_f16<1, 256>, cudaFuncAttributeMaxDynamicSharedMemorySize, SM_256);
    cudaFuncSetAttribute(gemm_f16<2, 256>, cudaFuncAttributeMaxDynamicSharedMemorySize, SM_256);
    cudaFuncSetAttribute(gemm_f16<3, 128>, cudaFuncAttributeMaxDynamicSharedMemorySize, SM_128);
    cudaFuncSetAttribute(gemm_f16<0, 256>, cudaFuncAttributeMaxDynamicSharedMemorySize, SM_256);
    cudaFuncSetAttribute(attn_tc, cudaFuncAttributeMaxDynamicSharedMemorySize, ATT_SMEM);

    // Launch order chosen so launch #5 (ncu -s window) is the layer-0 qkv GEMM.
    // 1: cvt_attn, 2: cvt_proj, 3: embed, 4: ln1(l0), 5: qkv(l0)
    cvt_wT16<<<dim3(3 * DMODEL / 32, DMODEL / 32, NLAYER), dim3(32, 8)>>>(
        attn_w, pwT16 + OFF_ATTN, DMODEL, 3 * DMODEL);
    cvt_wT16<<<dim3(DMODEL / 32, DMODEL / 32, NLAYER), dim3(32, 8)>>>(
        proj_w, pwT16 + OFF_PROJ, DMODEL, DMODEL);
    embed_kernel<<<NTOK, 256>>>(idx, wte, wpe);
    ln_kernel<<<NTOK, 256>>>(px, ln1_s, ln1_b, ph16);
    gemm_f16<1, 256><<<dim3(NTOK / 256, 3 * DMODEL / 128), 512, SM_256>>>(
        ph16, pwT16 + OFF_ATTN, attn_b, nullptr, pq16, 3 * DMODEL, DMODEL);
    // remaining conversions (before first use of fc/proj2 weights in layer 0)
    cvt_wT16<<<dim3(4 * DMODEL / 32, DMODEL / 32, NLAYER), dim3(32, 8)>>>(
        fc_w, pwT16 + OFF_FC, DMODEL, 4 * DMODEL);
    cvt_wT16<<<dim3(DMODEL / 32, 4 * DMODEL / 32, NLAYER), dim3(32, 8)>>>(
        proj2_w, pwT16 + OFF_PROJ2, 4 * DMODEL, DMODEL);
    {
        size_t nw = (size_t)VPAD * DMODEL;
        cvt_wte16<<<(unsigned)((nw + 255) / 256), 256>>>(wte);
    }

    for (int l = 0; l < NLAYER; l++) {
        const float* ab  = attn_b  + (size_t)l * 3 * DMODEL;
        const float* pb  = proj_b  + (size_t)l * DMODEL;
        const float* fb  = fc_b    + (size_t)l * 4 * DMODEL;
        const float* p2b = proj2_b + (size_t)l * DMODEL;
        size_t oAttn  = OFF_ATTN  + (size_t)l * SZ_ATTN;
        size_t oProj  = OFF_PROJ  + (size_t)l * SZ_PROJ;
        size_t oFc    = OFF_FC    + (size_t)l * SZ_FC;
        size_t oProj2 = OFF_PROJ2 + (size_t)l * SZ_PROJ2;

        // --- attention block (layer 0: ln1+qkv already issued above) ---
        if (l > 0) {
            ln_kernel<<<NTOK, 256>>>(px, ln1_s + l * DMODEL, ln1_b + l * DMODEL, ph16);
            gemm_f16<1, 256><<<dim3(NTOK / 256, 3 * DMODEL / 128), 512, SM_256>>>(
                ph16, pwT16 + oAttn, ab, nullptr, pq16, 3 * DMODEL, DMODEL);
        }
        attn_tc<<<dim3(SEQ / 64, NHEAD, 2), 128, ATT_SMEM>>>(pq16, py16);
        gemm_f16<3, 128><<<dim3(NTOK / 128, DMODEL / 128), 512, SM_128>>>(
            py16, pwT16 + oProj, pb, px, nullptr, DMODEL, DMODEL);

        // --- MLP block ---
        ln_kernel<<<NTOK, 256>>>(px, ln2_s + l * DMODEL, ln2_b + l * DMODEL, ph16);
        gemm_f16<2, 256><<<dim3(NTOK / 256, 4 * DMODEL / 128), 512, SM_256>>>(
            ph16, pwT16 + oFc, fb, nullptr, pm16, 4 * DMODEL, DMODEL);
        gemm_f16<3, 128><<<dim3(NTOK / 128, DMODEL / 128), 512, SM_128>>>(
            pm16, pwT16 + oProj2, p2b, px, nullptr, DMODEL, 4 * DMODEL);
    }

    // --- final LN + tied lm_head (fp16, fused loss partials) + loss ---
    ln_kernel<<<NTOK, 256>>>(px, lnf_s, lnf_b, ph16);
    gemm_f16<0, 256><<<dim3(NTOK / 256, VPAD / 128), 512, SM_256>>>(
        ph16, pwte16, nullptr, out, nullptr, VOCAB, DMODEL);

    lossrow2<<<NTOK, 128>>>(out, targets);
    lossreduce_kernel<<<1, 256>>>(out + (size_t)NTOK * VOCAB);
}